// round 15
// baseline (speedup 1.0000x reference)
#include <cuda_runtime.h>
#include <cuda_fp16.h>
#include <math.h>
#include <math_constants.h>
#include <stdint.h>

#define BATCH  2
#define SDIM   2048
#define DMODEL 1024
#define NHEADS 16
#define HDIM   64
#define MTOT   (BATCH * SDIM)          // 4096
#define SLOTSZ (MTOT * DMODEL)
#define WEL    (DMODEL * DMODEL)

// ---------------- scratch (all plain fp16) ----------------
__device__ __half g_xh[SLOTSZ];
__device__ __half g_qkvh[3 * SLOTSZ];  // slot 0=Q(pre-scaled),1=K,2=V
__device__ __half g_ah[SLOTSZ];        // attention out
__device__ __half g_whi[4 * WEL];      // W^T slots: q,k,v,o

// ---------------- PTX helpers ----------------
__device__ __forceinline__ uint32_t smem_u32(const void* p) {
    uint32_t a;
    asm("{ .reg .u64 t; cvta.to.shared.u64 t, %1; cvt.u32.u64 %0, t; }"
        : "=r"(a) : "l"(p));
    return a;
}
__device__ __forceinline__ void cp16(uint32_t dst, const void* src) {
    asm volatile("cp.async.ca.shared.global [%0], [%1], 16;"
                 :: "r"(dst), "l"(src) : "memory");
}
#define CP_COMMIT() asm volatile("cp.async.commit_group;" ::: "memory")
#define CP_WAIT3()  asm volatile("cp.async.wait_group 3;" ::: "memory")
#define CP_WAIT2()  asm volatile("cp.async.wait_group 2;" ::: "memory")
#define CP_WAIT1()  asm volatile("cp.async.wait_group 1;" ::: "memory")
#define CP_WAIT0()  asm volatile("cp.async.wait_group 0;" ::: "memory")

__device__ __forceinline__ void ldm_x4(uint32_t& r0, uint32_t& r1,
                                       uint32_t& r2, uint32_t& r3, uint32_t a) {
    asm volatile("ldmatrix.sync.aligned.m8n8.x4.shared.b16 {%0,%1,%2,%3}, [%4];"
                 : "=r"(r0), "=r"(r1), "=r"(r2), "=r"(r3) : "r"(a));
}
__device__ __forceinline__ void ldm_x4t(uint32_t& r0, uint32_t& r1,
                                        uint32_t& r2, uint32_t& r3, uint32_t a) {
    asm volatile("ldmatrix.sync.aligned.m8n8.x4.trans.shared.b16 {%0,%1,%2,%3}, [%4];"
                 : "=r"(r0), "=r"(r1), "=r"(r2), "=r"(r3) : "r"(a));
}
__device__ __forceinline__ void mma_f16(float* d, const uint32_t* a,
                                        uint32_t b0, uint32_t b1) {
    asm volatile(
        "mma.sync.aligned.m16n8k16.row.col.f32.f16.f16.f32 "
        "{%0,%1,%2,%3}, {%4,%5,%6,%7}, {%8,%9}, {%0,%1,%2,%3};"
        : "+f"(d[0]), "+f"(d[1]), "+f"(d[2]), "+f"(d[3])
        : "r"(a[0]), "r"(a[1]), "r"(a[2]), "r"(a[3]), "r"(b0), "r"(b1));
}
__device__ __forceinline__ uint32_t packh(float a, float b) {
    __half2 t = __floats2half2_rn(a, b);
    return *(uint32_t*)&t;
}

// =================================================================
// cast fp32 -> fp16
// =================================================================
__global__ __launch_bounds__(256) void cast_kernel(
    const float* __restrict__ in, __half* __restrict__ out, int n)
{
    int i = (blockIdx.x * 256 + threadIdx.x) * 4;
    if (i >= n) return;
    float4 v = *(const float4*)(in + i);
    *(__half2*)(out + i) = __floats2half2_rn(v.x, v.y);
    *(__half2*)(out + i + 2) = __floats2half2_rn(v.z, v.w);
}

// =================================================================
// batched transpose: all 4 weights in one launch (z selects W).
// =================================================================
__global__ __launch_bounds__(256) void tcast_all_kernel(
    const float* __restrict__ Wq, const float* __restrict__ Wk,
    const float* __restrict__ Wv, const float* __restrict__ Wo,
    __half* __restrict__ hibase)
{
    const int z = blockIdx.z;
    const float* W = (z == 0) ? Wq : (z == 1) ? Wk : (z == 2) ? Wv : Wo;
    __half* hi = hibase + (size_t)z * WEL;

    __shared__ float t[32][33];
    const int nt = blockIdx.x * 32, kt = blockIdx.y * 32;
    const int x = threadIdx.x, y = threadIdx.y;
#pragma unroll
    for (int i = 0; i < 4; i++)
        t[y + i * 8][x] = W[(size_t)(kt + y + i * 8) * DMODEL + nt + x];
    __syncthreads();
#pragma unroll
    for (int i = 0; i < 4; i++)
        hi[(size_t)(nt + y + i * 8) * DMODEL + kt + x] =
            __float2half(t[x][y + i * 8]);
}

// =================================================================
// plain fp16 GEMM.  CTA 128x128, BK=32, 8 warps (4m x 2n),
// warp tile 32x64, 1 MMA per k16-step.  4-stage cp.async, 2 CTAs/SM.
// MODE 0: fp32 out + bias.  MODE 1: fp16 out with QKV slot remap;
//         Q slot pre-scaled by 1/32 (fp16-exact).
// =================================================================
#define ST_A   (128 * 80)             // 10240 B
#define ST_B   (128 * 80)             // 10240 B
#define ST_SZ  (ST_A + ST_B)          // 20480 B per stage
#define OFF_B  ST_A
#define G_STAGES 4
#define ASCALE 0.03125f

template <int MODE>
__global__ __launch_bounds__(256, 2) void gemm_mma_kernel(
    const __half* __restrict__ A, const __half* __restrict__ B,
    const float* __restrict__ bias, float* __restrict__ C,
    __half* __restrict__ Ch, int M, int N, int K)
{
    extern __shared__ __align__(128) char smem[];
    const uint32_t sb = smem_u32(smem);
    const int tid = threadIdx.x;
    const int wid = tid >> 5, lane = tid & 31;
    const int wm = wid & 3, wn = wid >> 2;
    const int m0 = blockIdx.y * 128, n0 = blockIdx.x * 128;
    const int lrow = lane & 15, lcolb = (lane >> 4) * 16;

    float acc[2][8][4];
#pragma unroll
    for (int mt = 0; mt < 2; mt++)
#pragma unroll
        for (int nt = 0; nt < 8; nt++)
#pragma unroll
            for (int j = 0; j < 4; j++) acc[mt][nt][j] = 0.f;

    const int nchunks = K >> 5;

    auto issue = [&](int c) {
        const int k0 = c << 5;
        const uint32_t st = sb + (uint32_t)((c % G_STAGES) * ST_SZ);
#pragma unroll
        for (int i = 0; i < 2; i++) {
            int idx = tid + i * 256;          // 0..511
            int r = idx >> 2, kc = idx & 3;
            uint32_t so = (uint32_t)(r * 80 + kc * 16);
            cp16(st + so, A + (size_t)(m0 + r) * K + k0 + kc * 8);
            cp16(st + OFF_B + so, B + (size_t)(n0 + r) * K + k0 + kc * 8);
        }
        CP_COMMIT();
    };

    issue(0);
    issue(1);
    issue(2);
    issue(3);

    for (int c = 0; c < nchunks; c++) {
        if (c + 3 < nchunks) CP_WAIT3();
        else if (c + 2 < nchunks) CP_WAIT2();
        else if (c + 1 < nchunks) CP_WAIT1();
        else CP_WAIT0();
        __syncthreads();

        const uint32_t st = sb + (uint32_t)((c % G_STAGES) * ST_SZ);
        const uint32_t aBase = st + (uint32_t)((wm * 32 + lrow) * 80) + lcolb;
        const uint32_t bBase = st + OFF_B + (uint32_t)((wn * 64 + lrow) * 80) + lcolb;

#pragma unroll
        for (int ks = 0; ks < 2; ks++) {
            const uint32_t kb = ks * 32;
            uint32_t ah[2][4];
#pragma unroll
            for (int mt = 0; mt < 2; mt++)
                ldm_x4(ah[mt][0], ah[mt][1], ah[mt][2], ah[mt][3],
                       aBase + (uint32_t)(mt * 16 * 80) + kb);
#pragma unroll
            for (int g = 0; g < 4; g++) {
                uint32_t r0, r1, r2, r3;
                ldm_x4(r0, r1, r2, r3, bBase + (uint32_t)(g * 16 * 80) + kb);
#pragma unroll
                for (int mt = 0; mt < 2; mt++) {
                    mma_f16(acc[mt][2 * g + 0], ah[mt], r0, r2);
                    mma_f16(acc[mt][2 * g + 1], ah[mt], r1, r3);
                }
            }
        }
        __syncthreads();
        if (c + 4 < nchunks) issue(c + 4);
    }

    const int rbase = m0 + wm * 32 + (lane >> 2);
    const int cb0 = n0 + wn * 64 + 2 * (lane & 3);
#pragma unroll
    for (int mt = 0; mt < 2; mt++)
#pragma unroll
        for (int nt = 0; nt < 8; nt++) {
            int col = cb0 + nt * 8;
            int r0 = rbase + mt * 16;
            if (MODE == 0) {
                float b0 = bias[col], b1 = bias[col + 1];
                float2 v0 = { acc[mt][nt][0] + b0, acc[mt][nt][1] + b1 };
                float2 v1 = { acc[mt][nt][2] + b0, acc[mt][nt][3] + b1 };
                *(float2*)&C[(size_t)r0 * N + col] = v0;
                *(float2*)&C[(size_t)(r0 + 8) * N + col] = v1;
            } else {
                int slot = col >> 10, coll = col & 1023;
                size_t obh = (size_t)slot * SLOTSZ + (size_t)coll;
                float sc = (slot == 0) ? ASCALE : 1.0f;
#pragma unroll
                for (int half = 0; half < 2; half++) {
                    int rr = r0 + half * 8;
                    __half2 hp = __floats2half2_rn(acc[mt][nt][2 * half] * sc,
                                                   acc[mt][nt][2 * half + 1] * sc);
                    *(__half2*)&Ch[obh + (size_t)rr * DMODEL] = hp;
                }
            }
        }
}

// =================================================================
// Tensor-core flash attention, plain fp16, 4-stage pipeline, 2 CTAs/SM.
// Fixed-base softmax (Q pre-scaled; |s| bounded -> exp(s) direct).
// Warp-uniform mask branch: interior tiles skip all mask predicates.
// Scores: 1 MMA.  PV: 1 MMA.  CTA: 128 q x one (b,h).  K/V tiles 64.
// =================================================================
#define AT_ROW 144
#define AT_MAT (64 * AT_ROW)          // 9216
#define AT_STAGE (2 * AT_MAT)         // 18432
#define AT_STAGES 4

__global__ __launch_bounds__(256, 2) void attn_mma_kernel(
    const __half* __restrict__ qkvh, __half* __restrict__ oh)
{
    extern __shared__ __align__(128) char smem[];
    const uint32_t sb = smem_u32(smem);
    const int tid = threadIdx.x;
    const int wid = tid >> 5, lane = tid & 31;
    const int q0 = (int)(gridDim.x - 1 - blockIdx.x) * 128;
    const int h = blockIdx.y, b = blockIdx.z;

    const size_t base = (size_t)(b * SDIM) * DMODEL + h * HDIM;
    const __half* Qh = qkvh + base;
    const __half* Kh = qkvh + SLOTSZ + base;
    const __half* Vh = qkvh + 2 * SLOTSZ + base;

    // ---- stage Q through smem (stage-0 region; consumed before issue) ----
#pragma unroll
    for (int i = 0; i < 4; i++) {
        int idx = tid + i * 256;               // 0..1023
        int r = idx >> 3, c = idx & 7;
        size_t go = (size_t)(q0 + r) * DMODEL + c * 8;
        cp16(sb + (uint32_t)(r * AT_ROW + c * 16), Qh + go);
    }
    CP_COMMIT(); CP_WAIT0();
    __syncthreads();

    uint32_t qf[4][4];
    {
        uint32_t qa = sb + (uint32_t)((wid * 16 + (lane & 15)) * AT_ROW)
                         + (uint32_t)((lane >> 4) * 16);
#pragma unroll
        for (int ks = 0; ks < 4; ks++)
            ldm_x4(qf[ks][0], qf[ks][1], qf[ks][2], qf[ks][3], qa + ks * 32);
    }
    __syncthreads();

    auto issue = [&](int it) {
        const int k0 = it * 64;
        const uint32_t st = sb + (uint32_t)((it % AT_STAGES) * AT_STAGE);
#pragma unroll
        for (int i = 0; i < 2; i++) {
            int idx = tid + i * 256;           // 0..511
            int r = idx >> 3, c = idx & 7;
            size_t go = (size_t)(k0 + r) * DMODEL + c * 8;
            uint32_t so = (uint32_t)(r * AT_ROW + c * 16);
            cp16(st + 0 * AT_MAT + so, Kh + go);
            cp16(st + 1 * AT_MAT + so, Vh + go);
        }
        CP_COMMIT();
    };

    float l_r[2] = { 0.f, 0.f };
    float oc[8][4];
#pragma unroll
    for (int j = 0; j < 8; j++)
#pragma unroll
        for (int v = 0; v < 4; v++) oc[j][v] = 0.f;

    const int niters = (q0 >> 6) + 2;
    issue(0);
    if (niters > 1) issue(1);
    if (niters > 2) issue(2);
    if (niters > 3) issue(3);

    const int r0g = q0 + wid * 16 + (lane >> 2);
    const int r1g = r0g + 8;
    const int wrow_min = q0 + wid * 16;        // min row in this warp's tile
    const int wrow_max = wrow_min + 15;

    for (int it = 0; it < niters; it++) {
        if (it + 3 < niters) CP_WAIT3();
        else if (it + 2 < niters) CP_WAIT2();
        else if (it + 1 < niters) CP_WAIT1();
        else CP_WAIT0();
        __syncthreads();
        const int k0 = it * 64;

        if (k0 <= wrow_max) {
            const uint32_t st = sb + (uint32_t)((it % AT_STAGES) * AT_STAGE);
            const uint32_t kBase = st + (uint32_t)((lane & 15) * AT_ROW)
                                      + (uint32_t)((lane >> 4) * 16);
            const uint32_t vBase = kBase + AT_MAT;

            // ---- S = Q @ K^T (1 MMA; scale pre-folded into Q) ----
            float sc[8][4];
#pragma unroll
            for (int j = 0; j < 8; j++)
#pragma unroll
                for (int v = 0; v < 4; v++) sc[j][v] = 0.f;

#pragma unroll
            for (int ks = 0; ks < 4; ks++) {
                uint32_t bh[8][2];
#pragma unroll
                for (int g = 0; g < 4; g++) {
                    uint32_t r0, r1, r2, r3;
                    ldm_x4(r0, r1, r2, r3, kBase + (uint32_t)(g * 16 * AT_ROW) + ks * 32);
                    bh[2 * g + 0][0] = r0; bh[2 * g + 0][1] = r2;
                    bh[2 * g + 1][0] = r1; bh[2 * g + 1][1] = r3;
                }
#pragma unroll
                for (int j = 0; j < 8; j++)
                    mma_f16(sc[j], qf[ks], bh[j][0], bh[j][1]);
            }

            // ---- fixed-base softmax: P = exp(s); warp-uniform mask branch ----
            float s0 = 0.f, s1 = 0.f;
            if (k0 + 63 <= wrow_min) {
                // interior tile: no masking needed anywhere in this warp tile
#pragma unroll
                for (int j = 0; j < 8; j++) {
                    float e0 = __expf(sc[j][0]);
                    float e1 = __expf(sc[j][1]);
                    float e2 = __expf(sc[j][2]);
                    float e3 = __expf(sc[j][3]);
                    s0 += e0 + e1; s1 += e2 + e3;
                    sc[j][0] = __uint_as_float(packh(e0, e1));
                    sc[j][1] = __uint_as_float(packh(e2, e3));
                }
            } else {
                const int cb = k0 + 2 * (lane & 3);
#pragma unroll
                for (int j = 0; j < 8; j++) {
                    int c0 = cb + 8 * j, c1 = c0 + 1;
                    float e0 = (c0 <= r0g) ? __expf(sc[j][0]) : 0.f;
                    float e1 = (c1 <= r0g) ? __expf(sc[j][1]) : 0.f;
                    float e2 = (c0 <= r1g) ? __expf(sc[j][2]) : 0.f;
                    float e3 = (c1 <= r1g) ? __expf(sc[j][3]) : 0.f;
                    s0 += e0 + e1; s1 += e2 + e3;
                    sc[j][0] = __uint_as_float(packh(e0, e1));
                    sc[j][1] = __uint_as_float(packh(e2, e3));
                }
            }
            l_r[0] += s0;
            l_r[1] += s1;

            // ---- O += P @ V (1 MMA) ----
#pragma unroll
            for (int ks = 0; ks < 4; ks++) {
                uint32_t vh[8][2];
#pragma unroll
                for (int g = 0; g < 4; g++) {
                    uint32_t r0, r1, r2, r3;
                    ldm_x4t(r0, r1, r2, r3, vBase + (uint32_t)(ks * 16 * AT_ROW) + g * 32);
                    vh[2 * g + 0][0] = r0; vh[2 * g + 0][1] = r1;
                    vh[2 * g + 1][0] = r2; vh[2 * g + 1][1] = r3;
                }
                uint32_t pa[4] = { __float_as_uint(sc[2 * ks][0]),
                                   __float_as_uint(sc[2 * ks][1]),
                                   __float_as_uint(sc[2 * ks + 1][0]),
                                   __float_as_uint(sc[2 * ks + 1][1]) };
#pragma unroll
                for (int j = 0; j < 8; j++)
                    mma_f16(oc[j], pa, vh[j][0], vh[j][1]);
            }
        }

        __syncthreads();
        if (it + 4 < niters) issue(it + 4);
    }

    // ---- epilogue ----
    float lt0 = l_r[0];
    lt0 += __shfl_xor_sync(0xffffffffu, lt0, 1);
    lt0 += __shfl_xor_sync(0xffffffffu, lt0, 2);
    float lt1 = l_r[1];
    lt1 += __shfl_xor_sync(0xffffffffu, lt1, 1);
    lt1 += __shfl_xor_sync(0xffffffffu, lt1, 2);
    float inv0 = 1.f / lt0, inv1 = 1.f / lt1;

    size_t ob0 = (size_t)(b * SDIM + r0g) * DMODEL + h * HDIM + 2 * (lane & 3);
    size_t ob1 = ob0 + (size_t)8 * DMODEL;
#pragma unroll
    for (int j = 0; j < 8; j++) {
        __half2 hp0 = __floats2half2_rn(oc[j][0] * inv0, oc[j][1] * inv0);
        __half2 hp1 = __floats2half2_rn(oc[j][2] * inv1, oc[j][3] * inv1);
        *(__half2*)&oh[ob0 + 8 * j] = hp0;
        *(__half2*)&oh[ob1 + 8 * j] = hp1;
    }
}

// =================================================================
extern "C" void kernel_launch(void* const* d_in, const int* in_sizes, int n_in,
                              void* d_out, int out_size)
{
    const float* x  = (const float*)d_in[0];
    const float* Wq = (const float*)d_in[1];
    const float* Wk = (const float*)d_in[2];
    const float* Wv = (const float*)d_in[3];
    const float* Wo = (const float*)d_in[4];
    const float* bo = (const float*)d_in[5];
    float* out = (float*)d_out;

    __half *pxh, *pqkvh, *pah, *pwh;
    cudaGetSymbolAddress((void**)&pxh, g_xh);
    cudaGetSymbolAddress((void**)&pqkvh, g_qkvh);
    cudaGetSymbolAddress((void**)&pah, g_ah);
    cudaGetSymbolAddress((void**)&pwh, g_whi);

    const int NEL = MTOT * DMODEL;

    cast_kernel<<<NEL / (256 * 4), 256>>>(x, pxh, NEL);
    dim3 tgrid(DMODEL / 32, DMODEL / 32, 4), tblk(32, 8);
    tcast_all_kernel<<<tgrid, tblk>>>(Wq, Wk, Wv, Wo, pwh);

    const int gsmem = G_STAGES * ST_SZ;   // 81920
    cudaFuncSetAttribute(gemm_mma_kernel<0>,
                         cudaFuncAttributeMaxDynamicSharedMemorySize, gsmem);
    cudaFuncSetAttribute(gemm_mma_kernel<1>,
                         cudaFuncAttributeMaxDynamicSharedMemorySize, gsmem);

    // fused QKV projection: N = 3072, fp16 out with slot remap + Q pre-scale
    dim3 gq(3 * DMODEL / 128, MTOT / 128);  // (24, 32)
    gemm_mma_kernel<1><<<gq, 256, gsmem>>>(pxh, pwh, nullptr, nullptr, pqkvh,
                                           MTOT, 3 * DMODEL, DMODEL);

    const int asmem = AT_STAGES * AT_STAGE; // 73728
    cudaFuncSetAttribute(attn_mma_kernel,
                         cudaFuncAttributeMaxDynamicSharedMemorySize, asmem);
    dim3 agrid(SDIM / 128, NHEADS, BATCH);  // (16, 16, 2)
    attn_mma_kernel<<<agrid, 256, asmem>>>(pqkvh, pah);

    dim3 go(DMODEL / 128, MTOT / 128);      // (8, 32)
    gemm_mma_kernel<0><<<go, 256, gsmem>>>(pah, pwh + 3 * WEL, bo, out, nullptr,
                                           MTOT, DMODEL, DMODEL);
}

// round 16
// speedup vs baseline: 1.0156x; 1.0156x over previous
#include <cuda_runtime.h>
#include <cuda_fp16.h>
#include <math.h>
#include <math_constants.h>
#include <stdint.h>

#define BATCH  2
#define SDIM   2048
#define DMODEL 1024
#define NHEADS 16
#define HDIM   64
#define MTOT   (BATCH * SDIM)          // 4096
#define SLOTSZ (MTOT * DMODEL)
#define WEL    (DMODEL * DMODEL)

// ---------------- scratch (all plain fp16) ----------------
__device__ __half g_xh[SLOTSZ];
__device__ __half g_qkvh[3 * SLOTSZ];  // slot 0=Q(pre-scaled),1=K,2=V
__device__ __half g_ah[SLOTSZ];        // attention out
__device__ __half g_whi[4 * WEL];      // W^T slots: q,k,v,o

// ---------------- PTX helpers ----------------
__device__ __forceinline__ uint32_t smem_u32(const void* p) {
    uint32_t a;
    asm("{ .reg .u64 t; cvta.to.shared.u64 t, %1; cvt.u32.u64 %0, t; }"
        : "=r"(a) : "l"(p));
    return a;
}
__device__ __forceinline__ void cp16(uint32_t dst, const void* src) {
    asm volatile("cp.async.ca.shared.global [%0], [%1], 16;"
                 :: "r"(dst), "l"(src) : "memory");
}
#define CP_COMMIT() asm volatile("cp.async.commit_group;" ::: "memory")
#define CP_WAIT3()  asm volatile("cp.async.wait_group 3;" ::: "memory")
#define CP_WAIT2()  asm volatile("cp.async.wait_group 2;" ::: "memory")
#define CP_WAIT1()  asm volatile("cp.async.wait_group 1;" ::: "memory")
#define CP_WAIT0()  asm volatile("cp.async.wait_group 0;" ::: "memory")

__device__ __forceinline__ void ldm_x4(uint32_t& r0, uint32_t& r1,
                                       uint32_t& r2, uint32_t& r3, uint32_t a) {
    asm volatile("ldmatrix.sync.aligned.m8n8.x4.shared.b16 {%0,%1,%2,%3}, [%4];"
                 : "=r"(r0), "=r"(r1), "=r"(r2), "=r"(r3) : "r"(a));
}
__device__ __forceinline__ void ldm_x4t(uint32_t& r0, uint32_t& r1,
                                        uint32_t& r2, uint32_t& r3, uint32_t a) {
    asm volatile("ldmatrix.sync.aligned.m8n8.x4.trans.shared.b16 {%0,%1,%2,%3}, [%4];"
                 : "=r"(r0), "=r"(r1), "=r"(r2), "=r"(r3) : "r"(a));
}
__device__ __forceinline__ void mma_f16(float* d, const uint32_t* a,
                                        uint32_t b0, uint32_t b1) {
    asm volatile(
        "mma.sync.aligned.m16n8k16.row.col.f32.f16.f16.f32 "
        "{%0,%1,%2,%3}, {%4,%5,%6,%7}, {%8,%9}, {%0,%1,%2,%3};"
        : "+f"(d[0]), "+f"(d[1]), "+f"(d[2]), "+f"(d[3])
        : "r"(a[0]), "r"(a[1]), "r"(a[2]), "r"(a[3]), "r"(b0), "r"(b1));
}
__device__ __forceinline__ uint32_t packh(float a, float b) {
    __half2 t = __floats2half2_rn(a, b);
    return *(uint32_t*)&t;
}

// =================================================================
// cast fp32 -> fp16
// =================================================================
__global__ __launch_bounds__(256) void cast_kernel(
    const float* __restrict__ in, __half* __restrict__ out, int n)
{
    int i = (blockIdx.x * 256 + threadIdx.x) * 4;
    if (i >= n) return;
    float4 v = *(const float4*)(in + i);
    *(__half2*)(out + i) = __floats2half2_rn(v.x, v.y);
    *(__half2*)(out + i + 2) = __floats2half2_rn(v.z, v.w);
}

// =================================================================
// batched transpose: all 4 weights in one launch (z selects W).
// =================================================================
__global__ __launch_bounds__(256) void tcast_all_kernel(
    const float* __restrict__ Wq, const float* __restrict__ Wk,
    const float* __restrict__ Wv, const float* __restrict__ Wo,
    __half* __restrict__ hibase)
{
    const int z = blockIdx.z;
    const float* W = (z == 0) ? Wq : (z == 1) ? Wk : (z == 2) ? Wv : Wo;
    __half* hi = hibase + (size_t)z * WEL;

    __shared__ float t[32][33];
    const int nt = blockIdx.x * 32, kt = blockIdx.y * 32;
    const int x = threadIdx.x, y = threadIdx.y;
#pragma unroll
    for (int i = 0; i < 4; i++)
        t[y + i * 8][x] = W[(size_t)(kt + y + i * 8) * DMODEL + nt + x];
    __syncthreads();
#pragma unroll
    for (int i = 0; i < 4; i++)
        hi[(size_t)(nt + y + i * 8) * DMODEL + kt + x] =
            __float2half(t[x][y + i * 8]);
}

// =================================================================
// plain fp16 GEMM.  CTA 128x128, BK=32, 8 warps (4m x 2n),
// warp tile 32x64, 1 MMA per k16-step.  3-stage cp.async, 2 CTAs/SM.
// MODE 0: fp32 out + bias.  MODE 1: fp16 out with QKV slot remap;
//         Q slot pre-scaled by 1/32 (fp16-exact).
// =================================================================
#define ST_A   (128 * 80)             // 10240 B
#define ST_B   (128 * 80)             // 10240 B
#define ST_SZ  (ST_A + ST_B)          // 20480 B per stage
#define OFF_B  ST_A
#define G_STAGES 3
#define ASCALE 0.03125f

template <int MODE>
__global__ __launch_bounds__(256, 2) void gemm_mma_kernel(
    const __half* __restrict__ A, const __half* __restrict__ B,
    const float* __restrict__ bias, float* __restrict__ C,
    __half* __restrict__ Ch, int M, int N, int K)
{
    extern __shared__ __align__(128) char smem[];
    const uint32_t sb = smem_u32(smem);
    const int tid = threadIdx.x;
    const int wid = tid >> 5, lane = tid & 31;
    const int wm = wid & 3, wn = wid >> 2;
    const int m0 = blockIdx.y * 128, n0 = blockIdx.x * 128;
    const int lrow = lane & 15, lcolb = (lane >> 4) * 16;

    float acc[2][8][4];
#pragma unroll
    for (int mt = 0; mt < 2; mt++)
#pragma unroll
        for (int nt = 0; nt < 8; nt++)
#pragma unroll
            for (int j = 0; j < 4; j++) acc[mt][nt][j] = 0.f;

    const int nchunks = K >> 5;

    auto issue = [&](int c) {
        const int k0 = c << 5;
        const uint32_t st = sb + (uint32_t)((c % G_STAGES) * ST_SZ);
#pragma unroll
        for (int i = 0; i < 2; i++) {
            int idx = tid + i * 256;          // 0..511
            int r = idx >> 2, kc = idx & 3;
            uint32_t so = (uint32_t)(r * 80 + kc * 16);
            cp16(st + so, A + (size_t)(m0 + r) * K + k0 + kc * 8);
            cp16(st + OFF_B + so, B + (size_t)(n0 + r) * K + k0 + kc * 8);
        }
        CP_COMMIT();
    };

    issue(0);
    issue(1);
    issue(2);

    for (int c = 0; c < nchunks; c++) {
        if (c + 2 < nchunks) CP_WAIT2();
        else if (c + 1 < nchunks) CP_WAIT1();
        else CP_WAIT0();
        __syncthreads();

        const uint32_t st = sb + (uint32_t)((c % G_STAGES) * ST_SZ);
        const uint32_t aBase = st + (uint32_t)((wm * 32 + lrow) * 80) + lcolb;
        const uint32_t bBase = st + OFF_B + (uint32_t)((wn * 64 + lrow) * 80) + lcolb;

#pragma unroll
        for (int ks = 0; ks < 2; ks++) {
            const uint32_t kb = ks * 32;
            uint32_t ah[2][4];
#pragma unroll
            for (int mt = 0; mt < 2; mt++)
                ldm_x4(ah[mt][0], ah[mt][1], ah[mt][2], ah[mt][3],
                       aBase + (uint32_t)(mt * 16 * 80) + kb);
#pragma unroll
            for (int g = 0; g < 4; g++) {
                uint32_t r0, r1, r2, r3;
                ldm_x4(r0, r1, r2, r3, bBase + (uint32_t)(g * 16 * 80) + kb);
#pragma unroll
                for (int mt = 0; mt < 2; mt++) {
                    mma_f16(acc[mt][2 * g + 0], ah[mt], r0, r2);
                    mma_f16(acc[mt][2 * g + 1], ah[mt], r1, r3);
                }
            }
        }
        __syncthreads();
        if (c + 3 < nchunks) issue(c + 3);
    }

    const int rbase = m0 + wm * 32 + (lane >> 2);
    const int cb0 = n0 + wn * 64 + 2 * (lane & 3);
#pragma unroll
    for (int mt = 0; mt < 2; mt++)
#pragma unroll
        for (int nt = 0; nt < 8; nt++) {
            int col = cb0 + nt * 8;
            int r0 = rbase + mt * 16;
            if (MODE == 0) {
                float b0 = bias[col], b1 = bias[col + 1];
                float2 v0 = { acc[mt][nt][0] + b0, acc[mt][nt][1] + b1 };
                float2 v1 = { acc[mt][nt][2] + b0, acc[mt][nt][3] + b1 };
                *(float2*)&C[(size_t)r0 * N + col] = v0;
                *(float2*)&C[(size_t)(r0 + 8) * N + col] = v1;
            } else {
                int slot = col >> 10, coll = col & 1023;
                size_t obh = (size_t)slot * SLOTSZ + (size_t)coll;
                float sc = (slot == 0) ? ASCALE : 1.0f;
#pragma unroll
                for (int half = 0; half < 2; half++) {
                    int rr = r0 + half * 8;
                    __half2 hp = __floats2half2_rn(acc[mt][nt][2 * half] * sc,
                                                   acc[mt][nt][2 * half + 1] * sc);
                    *(__half2*)&Ch[obh + (size_t)rr * DMODEL] = hp;
                }
            }
        }
}

// =================================================================
// Tensor-core flash attention, plain fp16, 4-stage pipeline, 2 CTAs/SM.
// Fixed-base softmax (Q pre-scaled; |s| bounded -> exp(s) direct).
// Warp-uniform mask branch: interior tiles skip all mask predicates.
// Scores: 1 MMA.  PV: 1 MMA.  CTA: 128 q x one (b,h).  K/V tiles 64.
// =================================================================
#define AT_ROW 144
#define AT_MAT (64 * AT_ROW)          // 9216
#define AT_STAGE (2 * AT_MAT)         // 18432
#define AT_STAGES 4

__global__ __launch_bounds__(256, 2) void attn_mma_kernel(
    const __half* __restrict__ qkvh, __half* __restrict__ oh)
{
    extern __shared__ __align__(128) char smem[];
    const uint32_t sb = smem_u32(smem);
    const int tid = threadIdx.x;
    const int wid = tid >> 5, lane = tid & 31;
    const int q0 = (int)(gridDim.x - 1 - blockIdx.x) * 128;
    const int h = blockIdx.y, b = blockIdx.z;

    const size_t base = (size_t)(b * SDIM) * DMODEL + h * HDIM;
    const __half* Qh = qkvh + base;
    const __half* Kh = qkvh + SLOTSZ + base;
    const __half* Vh = qkvh + 2 * SLOTSZ + base;

    // ---- stage Q through smem (stage-0 region; consumed before issue) ----
#pragma unroll
    for (int i = 0; i < 4; i++) {
        int idx = tid + i * 256;               // 0..1023
        int r = idx >> 3, c = idx & 7;
        size_t go = (size_t)(q0 + r) * DMODEL + c * 8;
        cp16(sb + (uint32_t)(r * AT_ROW + c * 16), Qh + go);
    }
    CP_COMMIT(); CP_WAIT0();
    __syncthreads();

    uint32_t qf[4][4];
    {
        uint32_t qa = sb + (uint32_t)((wid * 16 + (lane & 15)) * AT_ROW)
                         + (uint32_t)((lane >> 4) * 16);
#pragma unroll
        for (int ks = 0; ks < 4; ks++)
            ldm_x4(qf[ks][0], qf[ks][1], qf[ks][2], qf[ks][3], qa + ks * 32);
    }
    __syncthreads();

    auto issue = [&](int it) {
        const int k0 = it * 64;
        const uint32_t st = sb + (uint32_t)((it % AT_STAGES) * AT_STAGE);
#pragma unroll
        for (int i = 0; i < 2; i++) {
            int idx = tid + i * 256;           // 0..511
            int r = idx >> 3, c = idx & 7;
            size_t go = (size_t)(k0 + r) * DMODEL + c * 8;
            uint32_t so = (uint32_t)(r * AT_ROW + c * 16);
            cp16(st + 0 * AT_MAT + so, Kh + go);
            cp16(st + 1 * AT_MAT + so, Vh + go);
        }
        CP_COMMIT();
    };

    float l_r[2] = { 0.f, 0.f };
    float oc[8][4];
#pragma unroll
    for (int j = 0; j < 8; j++)
#pragma unroll
        for (int v = 0; v < 4; v++) oc[j][v] = 0.f;

    const int niters = (q0 >> 6) + 2;
    issue(0);
    if (niters > 1) issue(1);
    if (niters > 2) issue(2);
    if (niters > 3) issue(3);

    const int r0g = q0 + wid * 16 + (lane >> 2);
    const int r1g = r0g + 8;
    const int wrow_min = q0 + wid * 16;
    const int wrow_max = wrow_min + 15;

    for (int it = 0; it < niters; it++) {
        if (it + 3 < niters) CP_WAIT3();
        else if (it + 2 < niters) CP_WAIT2();
        else if (it + 1 < niters) CP_WAIT1();
        else CP_WAIT0();
        __syncthreads();
        const int k0 = it * 64;

        if (k0 <= wrow_max) {
            const uint32_t st = sb + (uint32_t)((it % AT_STAGES) * AT_STAGE);
            const uint32_t kBase = st + (uint32_t)((lane & 15) * AT_ROW)
                                      + (uint32_t)((lane >> 4) * 16);
            const uint32_t vBase = kBase + AT_MAT;

            // ---- S = Q @ K^T (1 MMA; scale pre-folded into Q) ----
            float sc[8][4];
#pragma unroll
            for (int j = 0; j < 8; j++)
#pragma unroll
                for (int v = 0; v < 4; v++) sc[j][v] = 0.f;

#pragma unroll
            for (int ks = 0; ks < 4; ks++) {
                uint32_t bh[8][2];
#pragma unroll
                for (int g = 0; g < 4; g++) {
                    uint32_t r0, r1, r2, r3;
                    ldm_x4(r0, r1, r2, r3, kBase + (uint32_t)(g * 16 * AT_ROW) + ks * 32);
                    bh[2 * g + 0][0] = r0; bh[2 * g + 0][1] = r2;
                    bh[2 * g + 1][0] = r1; bh[2 * g + 1][1] = r3;
                }
#pragma unroll
                for (int j = 0; j < 8; j++)
                    mma_f16(sc[j], qf[ks], bh[j][0], bh[j][1]);
            }

            // ---- fixed-base softmax: P = exp(s); warp-uniform mask branch ----
            float s0 = 0.f, s1 = 0.f;
            if (k0 + 63 <= wrow_min) {
#pragma unroll
                for (int j = 0; j < 8; j++) {
                    float e0 = __expf(sc[j][0]);
                    float e1 = __expf(sc[j][1]);
                    float e2 = __expf(sc[j][2]);
                    float e3 = __expf(sc[j][3]);
                    s0 += e0 + e1; s1 += e2 + e3;
                    sc[j][0] = __uint_as_float(packh(e0, e1));
                    sc[j][1] = __uint_as_float(packh(e2, e3));
                }
            } else {
                const int cb = k0 + 2 * (lane & 3);
#pragma unroll
                for (int j = 0; j < 8; j++) {
                    int c0 = cb + 8 * j, c1 = c0 + 1;
                    float e0 = (c0 <= r0g) ? __expf(sc[j][0]) : 0.f;
                    float e1 = (c1 <= r0g) ? __expf(sc[j][1]) : 0.f;
                    float e2 = (c0 <= r1g) ? __expf(sc[j][2]) : 0.f;
                    float e3 = (c1 <= r1g) ? __expf(sc[j][3]) : 0.f;
                    s0 += e0 + e1; s1 += e2 + e3;
                    sc[j][0] = __uint_as_float(packh(e0, e1));
                    sc[j][1] = __uint_as_float(packh(e2, e3));
                }
            }
            l_r[0] += s0;
            l_r[1] += s1;

            // ---- O += P @ V (1 MMA) ----
#pragma unroll
            for (int ks = 0; ks < 4; ks++) {
                uint32_t vh[8][2];
#pragma unroll
                for (int g = 0; g < 4; g++) {
                    uint32_t r0, r1, r2, r3;
                    ldm_x4t(r0, r1, r2, r3, vBase + (uint32_t)(ks * 16 * AT_ROW) + g * 32);
                    vh[2 * g + 0][0] = r0; vh[2 * g + 0][1] = r1;
                    vh[2 * g + 1][0] = r2; vh[2 * g + 1][1] = r3;
                }
                uint32_t pa[4] = { __float_as_uint(sc[2 * ks][0]),
                                   __float_as_uint(sc[2 * ks][1]),
                                   __float_as_uint(sc[2 * ks + 1][0]),
                                   __float_as_uint(sc[2 * ks + 1][1]) };
#pragma unroll
                for (int j = 0; j < 8; j++)
                    mma_f16(oc[j], pa, vh[j][0], vh[j][1]);
            }
        }

        __syncthreads();
        if (it + 4 < niters) issue(it + 4);
    }

    // ---- epilogue ----
    float lt0 = l_r[0];
    lt0 += __shfl_xor_sync(0xffffffffu, lt0, 1);
    lt0 += __shfl_xor_sync(0xffffffffu, lt0, 2);
    float lt1 = l_r[1];
    lt1 += __shfl_xor_sync(0xffffffffu, lt1, 1);
    lt1 += __shfl_xor_sync(0xffffffffu, lt1, 2);
    float inv0 = 1.f / lt0, inv1 = 1.f / lt1;

    size_t ob0 = (size_t)(b * SDIM + r0g) * DMODEL + h * HDIM + 2 * (lane & 3);
    size_t ob1 = ob0 + (size_t)8 * DMODEL;
#pragma unroll
    for (int j = 0; j < 8; j++) {
        __half2 hp0 = __floats2half2_rn(oc[j][0] * inv0, oc[j][1] * inv0);
        __half2 hp1 = __floats2half2_rn(oc[j][2] * inv1, oc[j][3] * inv1);
        *(__half2*)&oh[ob0 + 8 * j] = hp0;
        *(__half2*)&oh[ob1 + 8 * j] = hp1;
    }
}

// =================================================================
extern "C" void kernel_launch(void* const* d_in, const int* in_sizes, int n_in,
                              void* d_out, int out_size)
{
    const float* x  = (const float*)d_in[0];
    const float* Wq = (const float*)d_in[1];
    const float* Wk = (const float*)d_in[2];
    const float* Wv = (const float*)d_in[3];
    const float* Wo = (const float*)d_in[4];
    const float* bo = (const float*)d_in[5];
    float* out = (float*)d_out;

    __half *pxh, *pqkvh, *pah, *pwh;
    cudaGetSymbolAddress((void**)&pxh, g_xh);
    cudaGetSymbolAddress((void**)&pqkvh, g_qkvh);
    cudaGetSymbolAddress((void**)&pah, g_ah);
    cudaGetSymbolAddress((void**)&pwh, g_whi);

    const int NEL = MTOT * DMODEL;

    cast_kernel<<<NEL / (256 * 4), 256>>>(x, pxh, NEL);
    dim3 tgrid(DMODEL / 32, DMODEL / 32, 4), tblk(32, 8);
    tcast_all_kernel<<<tgrid, tblk>>>(Wq, Wk, Wv, Wo, pwh);

    const int gsmem = G_STAGES * ST_SZ;   // 61440
    cudaFuncSetAttribute(gemm_mma_kernel<0>,
                         cudaFuncAttributeMaxDynamicSharedMemorySize, gsmem);
    cudaFuncSetAttribute(gemm_mma_kernel<1>,
                         cudaFuncAttributeMaxDynamicSharedMemorySize, gsmem);

    // fused QKV projection: N = 3072, fp16 out with slot remap + Q pre-scale
    dim3 gq(3 * DMODEL / 128, MTOT / 128);  // (24, 32)
    gemm_mma_kernel<1><<<gq, 256, gsmem>>>(pxh, pwh, nullptr, nullptr, pqkvh,
                                           MTOT, 3 * DMODEL, DMODEL);

    const int asmem = AT_STAGES * AT_STAGE; // 73728
    cudaFuncSetAttribute(attn_mma_kernel,
                         cudaFuncAttributeMaxDynamicSharedMemorySize, asmem);
    dim3 agrid(SDIM / 128, NHEADS, BATCH);  // (16, 16, 2)
    attn_mma_kernel<<<agrid, 256, asmem>>>(pqkvh, pah);

    dim3 go(DMODEL / 128, MTOT / 128);      // (8, 32)
    gemm_mma_kernel<0><<<go, 256, gsmem>>>(pah, pwh + 3 * WEL, bo, out, nullptr,
                                           MTOT, DMODEL, DMODEL);
}

// round 17
// speedup vs baseline: 1.0895x; 1.0727x over previous
#include <cuda_runtime.h>
#include <cuda_fp16.h>
#include <math.h>
#include <math_constants.h>
#include <stdint.h>

#define BATCH  2
#define SDIM   2048
#define DMODEL 1024
#define NHEADS 16
#define HDIM   64
#define MTOT   (BATCH * SDIM)          // 4096
#define SLOTSZ (MTOT * DMODEL)
#define WEL    (DMODEL * DMODEL)

// ---------------- scratch (all plain fp16) ----------------
__device__ __half g_xh[SLOTSZ];
__device__ __half g_qkvh[3 * SLOTSZ];  // slot 0=Q(pre-scaled),1=K,2=V
__device__ __half g_ah[SLOTSZ];        // attention out
__device__ __half g_whi[4 * WEL];      // W^T slots: q,k,v,o

// ---------------- PTX helpers ----------------
__device__ __forceinline__ uint32_t smem_u32(const void* p) {
    uint32_t a;
    asm("{ .reg .u64 t; cvta.to.shared.u64 t, %1; cvt.u32.u64 %0, t; }"
        : "=r"(a) : "l"(p));
    return a;
}
__device__ __forceinline__ void cp16(uint32_t dst, const void* src) {
    asm volatile("cp.async.ca.shared.global [%0], [%1], 16;"
                 :: "r"(dst), "l"(src) : "memory");
}
#define CP_COMMIT() asm volatile("cp.async.commit_group;" ::: "memory")
#define CP_WAIT3()  asm volatile("cp.async.wait_group 3;" ::: "memory")
#define CP_WAIT2()  asm volatile("cp.async.wait_group 2;" ::: "memory")
#define CP_WAIT1()  asm volatile("cp.async.wait_group 1;" ::: "memory")
#define CP_WAIT0()  asm volatile("cp.async.wait_group 0;" ::: "memory")

__device__ __forceinline__ void ldm_x4(uint32_t& r0, uint32_t& r1,
                                       uint32_t& r2, uint32_t& r3, uint32_t a) {
    asm volatile("ldmatrix.sync.aligned.m8n8.x4.shared.b16 {%0,%1,%2,%3}, [%4];"
                 : "=r"(r0), "=r"(r1), "=r"(r2), "=r"(r3) : "r"(a));
}
__device__ __forceinline__ void ldm_x4t(uint32_t& r0, uint32_t& r1,
                                        uint32_t& r2, uint32_t& r3, uint32_t a) {
    asm volatile("ldmatrix.sync.aligned.m8n8.x4.trans.shared.b16 {%0,%1,%2,%3}, [%4];"
                 : "=r"(r0), "=r"(r1), "=r"(r2), "=r"(r3) : "r"(a));
}
__device__ __forceinline__ void mma_f16(float* d, const uint32_t* a,
                                        uint32_t b0, uint32_t b1) {
    asm volatile(
        "mma.sync.aligned.m16n8k16.row.col.f32.f16.f16.f32 "
        "{%0,%1,%2,%3}, {%4,%5,%6,%7}, {%8,%9}, {%0,%1,%2,%3};"
        : "+f"(d[0]), "+f"(d[1]), "+f"(d[2]), "+f"(d[3])
        : "r"(a[0]), "r"(a[1]), "r"(a[2]), "r"(a[3]), "r"(b0), "r"(b1));
}
__device__ __forceinline__ uint32_t packh(float a, float b) {
    __half2 t = __floats2half2_rn(a, b);
    return *(uint32_t*)&t;
}

// =================================================================
// cast fp32 -> fp16
// =================================================================
__global__ __launch_bounds__(256) void cast_kernel(
    const float* __restrict__ in, __half* __restrict__ out, int n)
{
    int i = (blockIdx.x * 256 + threadIdx.x) * 4;
    if (i >= n) return;
    float4 v = *(const float4*)(in + i);
    *(__half2*)(out + i) = __floats2half2_rn(v.x, v.y);
    *(__half2*)(out + i + 2) = __floats2half2_rn(v.z, v.w);
}

// =================================================================
// batched transpose: all 4 weights in one launch (z selects W).
// =================================================================
__global__ __launch_bounds__(256) void tcast_all_kernel(
    const float* __restrict__ Wq, const float* __restrict__ Wk,
    const float* __restrict__ Wv, const float* __restrict__ Wo,
    __half* __restrict__ hibase)
{
    const int z = blockIdx.z;
    const float* W = (z == 0) ? Wq : (z == 1) ? Wk : (z == 2) ? Wv : Wo;
    __half* hi = hibase + (size_t)z * WEL;

    __shared__ float t[32][33];
    const int nt = blockIdx.x * 32, kt = blockIdx.y * 32;
    const int x = threadIdx.x, y = threadIdx.y;
#pragma unroll
    for (int i = 0; i < 4; i++)
        t[y + i * 8][x] = W[(size_t)(kt + y + i * 8) * DMODEL + nt + x];
    __syncthreads();
#pragma unroll
    for (int i = 0; i < 4; i++)
        hi[(size_t)(nt + y + i * 8) * DMODEL + kt + x] =
            __float2half(t[x][y + i * 8]);
}

// =================================================================
// plain fp16 GEMM.  CTA 128x128, BK=64, 8 warps (4m x 2n),
// warp tile 32x64, 1 MMA per k16-step.  2-stage cp.async, 2 CTAs/SM.
// Rows padded to 144B (same conflict-free layout as attn kernel).
// MODE 0: fp32 out + bias.  MODE 1: fp16 out with QKV slot remap;
//         Q slot pre-scaled by 1/32 (fp16-exact).
// =================================================================
#define GROW   144
#define ST_A   (128 * GROW)           // 18432 B
#define ST_SZ  (2 * ST_A)             // 36864 B per stage
#define OFF_B  ST_A
#define G_STAGES 2
#define ASCALE 0.03125f

template <int MODE>
__global__ __launch_bounds__(256, 2) void gemm_mma_kernel(
    const __half* __restrict__ A, const __half* __restrict__ B,
    const float* __restrict__ bias, float* __restrict__ C,
    __half* __restrict__ Ch, int M, int N, int K)
{
    extern __shared__ __align__(128) char smem[];
    const uint32_t sb = smem_u32(smem);
    const int tid = threadIdx.x;
    const int wid = tid >> 5, lane = tid & 31;
    const int wm = wid & 3, wn = wid >> 2;
    const int m0 = blockIdx.y * 128, n0 = blockIdx.x * 128;
    const int lrow = lane & 15, lcolb = (lane >> 4) * 16;

    float acc[2][8][4];
#pragma unroll
    for (int mt = 0; mt < 2; mt++)
#pragma unroll
        for (int nt = 0; nt < 8; nt++)
#pragma unroll
            for (int j = 0; j < 4; j++) acc[mt][nt][j] = 0.f;

    const int nchunks = K >> 6;   // BK=64

    auto issue = [&](int c) {
        const int k0 = c << 6;
        const uint32_t st = sb + (uint32_t)((c & 1) * ST_SZ);
#pragma unroll
        for (int i = 0; i < 4; i++) {
            int idx = tid + i * 256;          // 0..1023
            int r = idx >> 3, kc = idx & 7;
            uint32_t so = (uint32_t)(r * GROW + kc * 16);
            cp16(st + so, A + (size_t)(m0 + r) * K + k0 + kc * 8);
            cp16(st + OFF_B + so, B + (size_t)(n0 + r) * K + k0 + kc * 8);
        }
        CP_COMMIT();
    };

    issue(0);
    issue(1);

    for (int c = 0; c < nchunks; c++) {
        if (c + 1 < nchunks) CP_WAIT1(); else CP_WAIT0();
        __syncthreads();

        const uint32_t st = sb + (uint32_t)((c & 1) * ST_SZ);
        const uint32_t aBase = st + (uint32_t)((wm * 32 + lrow) * GROW) + lcolb;
        const uint32_t bBase = st + OFF_B + (uint32_t)((wn * 64 + lrow) * GROW) + lcolb;

#pragma unroll
        for (int ks = 0; ks < 4; ks++) {      // four k16-steps per BK=64
            const uint32_t kb = ks * 32;
            uint32_t ah[2][4];
#pragma unroll
            for (int mt = 0; mt < 2; mt++)
                ldm_x4(ah[mt][0], ah[mt][1], ah[mt][2], ah[mt][3],
                       aBase + (uint32_t)(mt * 16 * GROW) + kb);
#pragma unroll
            for (int g = 0; g < 4; g++) {
                uint32_t r0, r1, r2, r3;
                ldm_x4(r0, r1, r2, r3, bBase + (uint32_t)(g * 16 * GROW) + kb);
#pragma unroll
                for (int mt = 0; mt < 2; mt++) {
                    mma_f16(acc[mt][2 * g + 0], ah[mt], r0, r2);
                    mma_f16(acc[mt][2 * g + 1], ah[mt], r1, r3);
                }
            }
        }
        __syncthreads();
        if (c + 2 < nchunks) issue(c + 2);
    }

    const int rbase = m0 + wm * 32 + (lane >> 2);
    const int cb0 = n0 + wn * 64 + 2 * (lane & 3);
#pragma unroll
    for (int mt = 0; mt < 2; mt++)
#pragma unroll
        for (int nt = 0; nt < 8; nt++) {
            int col = cb0 + nt * 8;
            int r0 = rbase + mt * 16;
            if (MODE == 0) {
                float b0 = bias[col], b1 = bias[col + 1];
                float2 v0 = { acc[mt][nt][0] + b0, acc[mt][nt][1] + b1 };
                float2 v1 = { acc[mt][nt][2] + b0, acc[mt][nt][3] + b1 };
                *(float2*)&C[(size_t)r0 * N + col] = v0;
                *(float2*)&C[(size_t)(r0 + 8) * N + col] = v1;
            } else {
                int slot = col >> 10, coll = col & 1023;
                size_t obh = (size_t)slot * SLOTSZ + (size_t)coll;
                float sc = (slot == 0) ? ASCALE : 1.0f;
#pragma unroll
                for (int half = 0; half < 2; half++) {
                    int rr = r0 + half * 8;
                    __half2 hp = __floats2half2_rn(acc[mt][nt][2 * half] * sc,
                                                   acc[mt][nt][2 * half + 1] * sc);
                    *(__half2*)&Ch[obh + (size_t)rr * DMODEL] = hp;
                }
            }
        }
}

// =================================================================
// Tensor-core flash attention, plain fp16, 4-stage pipeline, 2 CTAs/SM.
// Fixed-base softmax (Q pre-scaled; |s| bounded -> exp(s) direct).
// Warp-uniform mask branch: interior tiles skip all mask predicates.
// Scores: 1 MMA.  PV: 1 MMA.  CTA: 128 q x one (b,h).  K/V tiles 64.
// =================================================================
#define AT_ROW 144
#define AT_MAT (64 * AT_ROW)          // 9216
#define AT_STAGE (2 * AT_MAT)         // 18432
#define AT_STAGES 4

__global__ __launch_bounds__(256, 2) void attn_mma_kernel(
    const __half* __restrict__ qkvh, __half* __restrict__ oh)
{
    extern __shared__ __align__(128) char smem[];
    const uint32_t sb = smem_u32(smem);
    const int tid = threadIdx.x;
    const int wid = tid >> 5, lane = tid & 31;
    const int q0 = (int)(gridDim.x - 1 - blockIdx.x) * 128;
    const int h = blockIdx.y, b = blockIdx.z;

    const size_t base = (size_t)(b * SDIM) * DMODEL + h * HDIM;
    const __half* Qh = qkvh + base;
    const __half* Kh = qkvh + SLOTSZ + base;
    const __half* Vh = qkvh + 2 * SLOTSZ + base;

    // ---- stage Q through smem (stage-0 region; consumed before issue) ----
#pragma unroll
    for (int i = 0; i < 4; i++) {
        int idx = tid + i * 256;               // 0..1023
        int r = idx >> 3, c = idx & 7;
        size_t go = (size_t)(q0 + r) * DMODEL + c * 8;
        cp16(sb + (uint32_t)(r * AT_ROW + c * 16), Qh + go);
    }
    CP_COMMIT(); CP_WAIT0();
    __syncthreads();

    uint32_t qf[4][4];
    {
        uint32_t qa = sb + (uint32_t)((wid * 16 + (lane & 15)) * AT_ROW)
                         + (uint32_t)((lane >> 4) * 16);
#pragma unroll
        for (int ks = 0; ks < 4; ks++)
            ldm_x4(qf[ks][0], qf[ks][1], qf[ks][2], qf[ks][3], qa + ks * 32);
    }
    __syncthreads();

    auto issue = [&](int it) {
        const int k0 = it * 64;
        const uint32_t st = sb + (uint32_t)((it % AT_STAGES) * AT_STAGE);
#pragma unroll
        for (int i = 0; i < 2; i++) {
            int idx = tid + i * 256;           // 0..511
            int r = idx >> 3, c = idx & 7;
            size_t go = (size_t)(k0 + r) * DMODEL + c * 8;
            uint32_t so = (uint32_t)(r * AT_ROW + c * 16);
            cp16(st + 0 * AT_MAT + so, Kh + go);
            cp16(st + 1 * AT_MAT + so, Vh + go);
        }
        CP_COMMIT();
    };

    float l_r[2] = { 0.f, 0.f };
    float oc[8][4];
#pragma unroll
    for (int j = 0; j < 8; j++)
#pragma unroll
        for (int v = 0; v < 4; v++) oc[j][v] = 0.f;

    const int niters = (q0 >> 6) + 2;
    issue(0);
    if (niters > 1) issue(1);
    if (niters > 2) issue(2);
    if (niters > 3) issue(3);

    const int r0g = q0 + wid * 16 + (lane >> 2);
    const int r1g = r0g + 8;
    const int wrow_min = q0 + wid * 16;
    const int wrow_max = wrow_min + 15;

    for (int it = 0; it < niters; it++) {
        if (it + 3 < niters) CP_WAIT3();
        else if (it + 2 < niters) CP_WAIT2();
        else if (it + 1 < niters) CP_WAIT1();
        else CP_WAIT0();
        __syncthreads();
        const int k0 = it * 64;

        if (k0 <= wrow_max) {
            const uint32_t st = sb + (uint32_t)((it % AT_STAGES) * AT_STAGE);
            const uint32_t kBase = st + (uint32_t)((lane & 15) * AT_ROW)
                                      + (uint32_t)((lane >> 4) * 16);
            const uint32_t vBase = kBase + AT_MAT;

            // ---- S = Q @ K^T (1 MMA; scale pre-folded into Q) ----
            float sc[8][4];
#pragma unroll
            for (int j = 0; j < 8; j++)
#pragma unroll
                for (int v = 0; v < 4; v++) sc[j][v] = 0.f;

#pragma unroll
            for (int ks = 0; ks < 4; ks++) {
                uint32_t bh[8][2];
#pragma unroll
                for (int g = 0; g < 4; g++) {
                    uint32_t r0, r1, r2, r3;
                    ldm_x4(r0, r1, r2, r3, kBase + (uint32_t)(g * 16 * AT_ROW) + ks * 32);
                    bh[2 * g + 0][0] = r0; bh[2 * g + 0][1] = r2;
                    bh[2 * g + 1][0] = r1; bh[2 * g + 1][1] = r3;
                }
#pragma unroll
                for (int j = 0; j < 8; j++)
                    mma_f16(sc[j], qf[ks], bh[j][0], bh[j][1]);
            }

            // ---- fixed-base softmax: P = exp(s); warp-uniform mask branch ----
            float s0 = 0.f, s1 = 0.f;
            if (k0 + 63 <= wrow_min) {
#pragma unroll
                for (int j = 0; j < 8; j++) {
                    float e0 = __expf(sc[j][0]);
                    float e1 = __expf(sc[j][1]);
                    float e2 = __expf(sc[j][2]);
                    float e3 = __expf(sc[j][3]);
                    s0 += e0 + e1; s1 += e2 + e3;
                    sc[j][0] = __uint_as_float(packh(e0, e1));
                    sc[j][1] = __uint_as_float(packh(e2, e3));
                }
            } else {
                const int cb = k0 + 2 * (lane & 3);
#pragma unroll
                for (int j = 0; j < 8; j++) {
                    int c0 = cb + 8 * j, c1 = c0 + 1;
                    float e0 = (c0 <= r0g) ? __expf(sc[j][0]) : 0.f;
                    float e1 = (c1 <= r0g) ? __expf(sc[j][1]) : 0.f;
                    float e2 = (c0 <= r1g) ? __expf(sc[j][2]) : 0.f;
                    float e3 = (c1 <= r1g) ? __expf(sc[j][3]) : 0.f;
                    s0 += e0 + e1; s1 += e2 + e3;
                    sc[j][0] = __uint_as_float(packh(e0, e1));
                    sc[j][1] = __uint_as_float(packh(e2, e3));
                }
            }
            l_r[0] += s0;
            l_r[1] += s1;

            // ---- O += P @ V (1 MMA) ----
#pragma unroll
            for (int ks = 0; ks < 4; ks++) {
                uint32_t vh[8][2];
#pragma unroll
                for (int g = 0; g < 4; g++) {
                    uint32_t r0, r1, r2, r3;
                    ldm_x4t(r0, r1, r2, r3, vBase + (uint32_t)(ks * 16 * AT_ROW) + g * 32);
                    vh[2 * g + 0][0] = r0; vh[2 * g + 0][1] = r1;
                    vh[2 * g + 1][0] = r2; vh[2 * g + 1][1] = r3;
                }
                uint32_t pa[4] = { __float_as_uint(sc[2 * ks][0]),
                                   __float_as_uint(sc[2 * ks][1]),
                                   __float_as_uint(sc[2 * ks + 1][0]),
                                   __float_as_uint(sc[2 * ks + 1][1]) };
#pragma unroll
                for (int j = 0; j < 8; j++)
                    mma_f16(oc[j], pa, vh[j][0], vh[j][1]);
            }
        }

        __syncthreads();
        if (it + 4 < niters) issue(it + 4);
    }

    // ---- epilogue ----
    float lt0 = l_r[0];
    lt0 += __shfl_xor_sync(0xffffffffu, lt0, 1);
    lt0 += __shfl_xor_sync(0xffffffffu, lt0, 2);
    float lt1 = l_r[1];
    lt1 += __shfl_xor_sync(0xffffffffu, lt1, 1);
    lt1 += __shfl_xor_sync(0xffffffffu, lt1, 2);
    float inv0 = 1.f / lt0, inv1 = 1.f / lt1;

    size_t ob0 = (size_t)(b * SDIM + r0g) * DMODEL + h * HDIM + 2 * (lane & 3);
    size_t ob1 = ob0 + (size_t)8 * DMODEL;
#pragma unroll
    for (int j = 0; j < 8; j++) {
        __half2 hp0 = __floats2half2_rn(oc[j][0] * inv0, oc[j][1] * inv0);
        __half2 hp1 = __floats2half2_rn(oc[j][2] * inv1, oc[j][3] * inv1);
        *(__half2*)&oh[ob0 + 8 * j] = hp0;
        *(__half2*)&oh[ob1 + 8 * j] = hp1;
    }
}

// =================================================================
extern "C" void kernel_launch(void* const* d_in, const int* in_sizes, int n_in,
                              void* d_out, int out_size)
{
    const float* x  = (const float*)d_in[0];
    const float* Wq = (const float*)d_in[1];
    const float* Wk = (const float*)d_in[2];
    const float* Wv = (const float*)d_in[3];
    const float* Wo = (const float*)d_in[4];
    const float* bo = (const float*)d_in[5];
    float* out = (float*)d_out;

    __half *pxh, *pqkvh, *pah, *pwh;
    cudaGetSymbolAddress((void**)&pxh, g_xh);
    cudaGetSymbolAddress((void**)&pqkvh, g_qkvh);
    cudaGetSymbolAddress((void**)&pah, g_ah);
    cudaGetSymbolAddress((void**)&pwh, g_whi);

    const int NEL = MTOT * DMODEL;

    cast_kernel<<<NEL / (256 * 4), 256>>>(x, pxh, NEL);
    dim3 tgrid(DMODEL / 32, DMODEL / 32, 4), tblk(32, 8);
    tcast_all_kernel<<<tgrid, tblk>>>(Wq, Wk, Wv, Wo, pwh);

    const int gsmem = G_STAGES * ST_SZ;   // 73728
    cudaFuncSetAttribute(gemm_mma_kernel<0>,
                         cudaFuncAttributeMaxDynamicSharedMemorySize, gsmem);
    cudaFuncSetAttribute(gemm_mma_kernel<1>,
                         cudaFuncAttributeMaxDynamicSharedMemorySize, gsmem);

    // fused QKV projection: N = 3072, fp16 out with slot remap + Q pre-scale
    dim3 gq(3 * DMODEL / 128, MTOT / 128);  // (24, 32)
    gemm_mma_kernel<1><<<gq, 256, gsmem>>>(pxh, pwh, nullptr, nullptr, pqkvh,
                                           MTOT, 3 * DMODEL, DMODEL);

    const int asmem = AT_STAGES * AT_STAGE; // 73728
    cudaFuncSetAttribute(attn_mma_kernel,
                         cudaFuncAttributeMaxDynamicSharedMemorySize, asmem);
    dim3 agrid(SDIM / 128, NHEADS, BATCH);  // (16, 16, 2)
    attn_mma_kernel<<<agrid, 256, asmem>>>(pqkvh, pah);

    dim3 go(DMODEL / 128, MTOT / 128);      // (8, 32)
    gemm_mma_kernel<0><<<go, 256, gsmem>>>(pah, pwh + 3 * WEL, bo, out, nullptr,
                                           MTOT, DMODEL, DMODEL);
}